// round 1
// baseline (speedup 1.0000x reference)
#include <cuda_runtime.h>
#include <math.h>
#include <stdint.h>

#define NPTS 8192
#define DDIM 512
#define ODIM 512

// Scratch in device globals (no allocations allowed anywhere).
__device__ float g_wmat[(size_t)NPTS * NPTS];     // 256 MiB Gaussian weight matrix
__device__ float g_rowsum[NPTS];
__device__ float g_sq[NPTS];
__device__ float g_out1[(size_t)NPTS * DDIM];     // 16 MiB Nadaraya-Watson output

// ---------------------------------------------------------------------------
// K1: per-row squared L2 norm of x, also zeroes rowsum accumulators.
// One warp per row, 8 rows per 256-thread block.
// ---------------------------------------------------------------------------
__global__ void __launch_bounds__(256) rownorm_kernel(const float* __restrict__ x)
{
    const int row  = blockIdx.x * 8 + (threadIdx.x >> 5);
    const int lane = threadIdx.x & 31;
    const float* xr = x + (size_t)row * DDIM;
    float s = 0.f;
#pragma unroll
    for (int d = lane; d < DDIM; d += 32) { float v = xr[d]; s = fmaf(v, v, s); }
#pragma unroll
    for (int o = 16; o > 0; o >>= 1) s += __shfl_xor_sync(0xffffffffu, s, o);
    if (lane == 0) { g_sq[row] = s; g_rowsum[row] = 0.f; }
}

// ---------------------------------------------------------------------------
// Generic 128x128x16 register-blocked SGEMM, 256 threads, 8x8 micro-tiles.
//   A: [M,K] row-major.
//   B: TRANSB ? [N,K] row-major (A.Bt) : [K,N] row-major (A.B).
// MODE 0: Gaussian-weight epilogue (uses g_sq, stores w, REDG row sums)
// MODE 1: divide by (rowsum + eps)
// MODE 2: add bias
// All dims are multiples of the tile sizes for this problem; no bounds checks.
// ---------------------------------------------------------------------------
template<int MODE, bool TRANSB>
__global__ void __launch_bounds__(256, 2) gemm_kernel(
    const float* __restrict__ A, const float* __restrict__ B,
    float* __restrict__ C, int M, int N, int K, const float* __restrict__ bias)
{
    constexpr int BM = 128, BN = 128, BK = 16;
    __shared__ float As[BK][BM];
    __shared__ float Bs[BK][BN];

    const int tid = threadIdx.x;
    const int tx  = tid & 15;        // 0..15 -> column group
    const int ty  = tid >> 4;        // 0..15 -> row group
    const int bm0 = blockIdx.y * BM;
    const int bn0 = blockIdx.x * BN;

    float acc[8][8] = {};

    for (int k0 = 0; k0 < K; k0 += BK) {
        // --- load A tile (128x16), store transposed As[k][m] ---
#pragma unroll
        for (int l = 0; l < 2; l++) {
            int idx = tid + l * 256;          // 0..511 float4 slots
            int r = idx >> 2, c = (idx & 3) * 4;
            float4 v = *reinterpret_cast<const float4*>(A + (size_t)(bm0 + r) * K + k0 + c);
            As[c + 0][r] = v.x; As[c + 1][r] = v.y; As[c + 2][r] = v.z; As[c + 3][r] = v.w;
        }
        // --- load B tile ---
        if (TRANSB) {
#pragma unroll
            for (int l = 0; l < 2; l++) {
                int idx = tid + l * 256;
                int r = idx >> 2, c = (idx & 3) * 4;
                float4 v = *reinterpret_cast<const float4*>(B + (size_t)(bn0 + r) * K + k0 + c);
                Bs[c + 0][r] = v.x; Bs[c + 1][r] = v.y; Bs[c + 2][r] = v.z; Bs[c + 3][r] = v.w;
            }
        } else {
#pragma unroll
            for (int l = 0; l < 2; l++) {
                int idx = tid + l * 256;
                int r = idx >> 5, c = (idx & 31) * 4;   // r: 0..15, c: 0..124
                float4 v = *reinterpret_cast<const float4*>(B + (size_t)(k0 + r) * N + bn0 + c);
                *reinterpret_cast<float4*>(&Bs[r][c]) = v;
            }
        }
        __syncthreads();

#pragma unroll
        for (int kk = 0; kk < BK; kk++) {
            float ra[8], rb[8];
#pragma unroll
            for (int i = 0; i < 8; i++) ra[i] = As[kk][ty * 8 + i];
#pragma unroll
            for (int j = 0; j < 8; j++) rb[j] = Bs[kk][tx * 8 + j];
#pragma unroll
            for (int i = 0; i < 8; i++)
#pragma unroll
                for (int j = 0; j < 8; j++)
                    acc[i][j] = fmaf(ra[i], rb[j], acc[i][j]);
        }
        __syncthreads();
    }

    const int row = bm0 + ty * 8;
    const int col = bn0 + tx * 8;

    if (MODE == 0) {
        // w = exp(-(max(sq_i + sq_j - 2*dot, 0)) / (2*sigma^2)), sigma = 32
        constexpr float NEG_INV2SIG2 = -1.0f / (2.0f * 32.0f * 32.0f);
        float sqi[8], sqj[8];
#pragma unroll
        for (int i = 0; i < 8; i++) sqi[i] = g_sq[row + i];
#pragma unroll
        for (int j = 0; j < 8; j++) sqj[j] = g_sq[col + j];
#pragma unroll
        for (int i = 0; i < 8; i++) {
            float w[8], rs = 0.f;
#pragma unroll
            for (int j = 0; j < 8; j++) {
                float sqd = fmaxf(sqi[i] + sqj[j] - 2.f * acc[i][j], 0.f);
                w[j] = __expf(sqd * NEG_INV2SIG2);
                rs += w[j];
            }
            float4* cp = reinterpret_cast<float4*>(C + (size_t)(row + i) * N + col);
            cp[0] = make_float4(w[0], w[1], w[2], w[3]);
            cp[1] = make_float4(w[4], w[5], w[6], w[7]);
            atomicAdd(&g_rowsum[row + i], rs);
        }
    } else if (MODE == 1) {
#pragma unroll
        for (int i = 0; i < 8; i++) {
            float inv = 1.f / (g_rowsum[row + i] + 1e-8f);
            float4* cp = reinterpret_cast<float4*>(C + (size_t)(row + i) * N + col);
            cp[0] = make_float4(acc[i][0] * inv, acc[i][1] * inv, acc[i][2] * inv, acc[i][3] * inv);
            cp[1] = make_float4(acc[i][4] * inv, acc[i][5] * inv, acc[i][6] * inv, acc[i][7] * inv);
        }
    } else {
        float bj[8];
#pragma unroll
        for (int j = 0; j < 8; j++) bj[j] = bias[col + j];
#pragma unroll
        for (int i = 0; i < 8; i++) {
            float4* cp = reinterpret_cast<float4*>(C + (size_t)(row + i) * N + col);
            cp[0] = make_float4(acc[i][0] + bj[0], acc[i][1] + bj[1], acc[i][2] + bj[2], acc[i][3] + bj[3]);
            cp[1] = make_float4(acc[i][4] + bj[4], acc[i][5] + bj[5], acc[i][6] + bj[6], acc[i][7] + bj[7]);
        }
    }
}

extern "C" void kernel_launch(void* const* d_in, const int* in_sizes, int n_in,
                              void* d_out, int out_size)
{
    const float* x  = (const float*)d_in[0];   // [8192, 512]
    const float* Wl = (const float*)d_in[1];   // [512, 512]
    const float* b  = (const float*)d_in[2];   // [512]
    float* out = (float*)d_out;                // [8192, 512]

    void *wmat_p, *out1_p;
    cudaGetSymbolAddress(&wmat_p, g_wmat);
    cudaGetSymbolAddress(&out1_p, g_out1);
    float* wmat = (float*)wmat_p;
    float* out1 = (float*)out1_p;

    // K1: row norms + zero rowsums
    rownorm_kernel<<<NPTS / 8, 256>>>(x);

    // K2: w = exp(-sqd/2s^2) via x.x^T GEMM; also accumulates rowsums
    gemm_kernel<0, true ><<<dim3(NPTS / 128, NPTS / 128), 256>>>(x, x, wmat, NPTS, NPTS, DDIM, nullptr);

    // K3: out1 = (w @ x) / (rowsum + eps)
    gemm_kernel<1, false><<<dim3(DDIM / 128, NPTS / 128), 256>>>(wmat, x, out1, NPTS, DDIM, NPTS, nullptr);

    // K4: out = out1 @ Wl^T + b
    gemm_kernel<2, true ><<<dim3(ODIM / 128, NPTS / 128), 256>>>(out1, Wl, out, NPTS, ODIM, DDIM, b);
}

// round 11
// speedup vs baseline: 6.0173x; 6.0173x over previous
#include <cuda_runtime.h>
#include <math.h>
#include <stdint.h>

#define NPTS 8192
#define DDIM 512
#define ODIM 512

// ---------------- device scratch (no allocations allowed) ----------------
__device__ float g_wmat[(size_t)NPTS * NPTS];   // 256 MiB gaussian weights (tf32-rounded)
__device__ float g_rowsum[NPTS];
__device__ float g_sq[NPTS];
__device__ float g_out1[(size_t)NPTS * DDIM];   // NW output (tf32-rounded)
__device__ float g_xr[(size_t)NPTS * DDIM];     // x rounded to tf32
__device__ float g_xT[(size_t)DDIM * NPTS];     // x^T rounded to tf32
__device__ float g_wlr[(size_t)ODIM * DDIM];    // W rounded to tf32

__device__ __forceinline__ float cvt_tf32_rn(float f) {
    uint32_t r; asm("cvt.rn.tf32.f32 %0, %1;" : "=r"(r) : "f"(f));
    return __uint_as_float(r);
}

// ---------------- prep kernels ----------------
__global__ void __launch_bounds__(256) prep_x_kernel(const float* __restrict__ x)
{
    const int row  = blockIdx.x * 8 + (threadIdx.x >> 5);
    const int lane = threadIdx.x & 31;
    const float* xr = x + (size_t)row * DDIM;
    float* xo = g_xr + (size_t)row * DDIM;
    float s = 0.f;
#pragma unroll
    for (int d = lane; d < DDIM; d += 32) {
        float v = xr[d];
        s = fmaf(v, v, s);
        xo[d] = cvt_tf32_rn(v);
    }
#pragma unroll
    for (int o = 16; o > 0; o >>= 1) s += __shfl_xor_sync(0xffffffffu, s, o);
    if (lane == 0) { g_sq[row] = s; g_rowsum[row] = 0.f; }
}

__global__ void __launch_bounds__(256) transpose_kernel()
{
    __shared__ float t[32][33];
    const int n0 = blockIdx.x * 32, d0 = blockIdx.y * 32;
    const int tx = threadIdx.x & 31, ty8 = threadIdx.x >> 5;
#pragma unroll
    for (int i = 0; i < 4; i++) {
        int r = ty8 + i * 8;
        t[r][tx] = g_xr[(size_t)(n0 + r) * DDIM + d0 + tx];
    }
    __syncthreads();
#pragma unroll
    for (int i = 0; i < 4; i++) {
        int r = ty8 + i * 8;
        g_xT[(size_t)(d0 + r) * NPTS + n0 + tx] = t[tx][r];
    }
}

__global__ void __launch_bounds__(256) prep_w_kernel(const float* __restrict__ W)
{
    int i = blockIdx.x * 256 + threadIdx.x;
#pragma unroll
    for (int l = 0; l < 4; l++) {
        int idx = i + l * 256 * 256;
        g_wlr[idx] = cvt_tf32_rn(W[idx]);
    }
}

// ---------------------------------------------------------------------------
// tf32 mma.sync GEMM:  C[M, Ntot] = A[M,K] . B[Ntot,K]^T   (all row-major)
// CTA tile 128x128x32, 8 warps (2 in N x 4 in M), warp tile 32x64.
// SMEM in mma-fragment-permuted order; kt-skew for bank spread.
// Region sizes PADDED to 4128 floats: max a_off = 4107, max b_off = 4101.
// ---------------------------------------------------------------------------
#define MMA_TF32(c, a, b) \
    asm volatile("mma.sync.aligned.m16n8k8.row.col.f32.tf32.tf32.f32 " \
        "{%0,%1,%2,%3}, {%4,%5,%6,%7}, {%8,%9}, {%0,%1,%2,%3};" \
        : "+f"((c)[0]), "+f"((c)[1]), "+f"((c)[2]), "+f"((c)[3]) \
        : "r"((a)[0]), "r"((a)[1]), "r"((a)[2]), "r"((a)[3]), \
          "r"((b)[0]), "r"((b)[1]))

__device__ __forceinline__ int a_off(int kt, int rt, int t) {
    return ((kt * 8 + rt) * 32 + t) * 4 + kt * 4;
}
__device__ __forceinline__ int b_off(int kt, int nt, int t) {
    return ((kt * 16 + nt) * 32 + t) * 2 + kt * 2;
}

template<int MODE>
__global__ void __launch_bounds__(256) hmma_gemm(
    const float* __restrict__ A, const float* __restrict__ B, float* __restrict__ C,
    int Ntot, int K, const float* __restrict__ bias)
{
    constexpr int BM = 128, BN = 128, BK = 32;
    constexpr int AREG = 4128;            // padded region (>= 4108), 16B aligned
    constexpr int STAGE_F = 2 * AREG;     // A region + B region per stage
    extern __shared__ float sm[];

    const int tid  = threadIdx.x;
    const int lane = tid & 31, wid = tid >> 5;
    const int wy = wid & 3;        // M warp coord (4)
    const int wx = wid >> 2;       // N warp coord (2)
    const int bm0 = blockIdx.y * BM;
    const int bn0 = blockIdx.x * BN;

    float c[2][8][4] = {};

    const int nchunk = K / BK;
    float4 ra[4], rb[4];

    // ---- prologue: load + store chunk 0 into stage 0 ----
#pragma unroll
    for (int l = 0; l < 4; l++) {
        int idx = tid + l * 256, rr = idx >> 3, c4 = idx & 7;
        ra[l] = *reinterpret_cast<const float4*>(A + (size_t)(bm0 + rr) * K + c4 * 4);
        rb[l] = *reinterpret_cast<const float4*>(B + (size_t)(bn0 + rr) * K + c4 * 4);
    }
    {
        float* sA = sm; float* sB = sm + AREG;
#pragma unroll
        for (int l = 0; l < 4; l++) {
            int idx = tid + l * 256, rr = idx >> 3, c4 = idx & 7;
            int kt = c4 >> 1, half = c4 & 1;
            int rt = rr >> 4, g = rr & 7, hi = (rr >> 3) & 1;
            int reg = hi + 2 * half;
            int ba = a_off(kt, rt, g * 4) + reg;
            sA[ba + 0] = ra[l].x; sA[ba + 4] = ra[l].y; sA[ba + 8] = ra[l].z; sA[ba + 12] = ra[l].w;
            int nt = rr >> 3, gb = rr & 7, regb = c4 & 1;
            int bb = b_off(kt, nt, gb * 4) + regb;
            sB[bb + 0] = rb[l].x; sB[bb + 2] = rb[l].y; sB[bb + 4] = rb[l].z; sB[bb + 6] = rb[l].w;
        }
    }
    __syncthreads();

    for (int ci = 0; ci < nchunk; ci++) {
        const int s = ci & 1;
        const int k0n = (ci + 1) * BK;
        if (ci + 1 < nchunk) {
#pragma unroll
            for (int l = 0; l < 4; l++) {
                int idx = tid + l * 256, rr = idx >> 3, c4 = idx & 7;
                ra[l] = *reinterpret_cast<const float4*>(A + (size_t)(bm0 + rr) * K + k0n + c4 * 4);
                rb[l] = *reinterpret_cast<const float4*>(B + (size_t)(bn0 + rr) * K + k0n + c4 * 4);
            }
        }
        // ---- compute current stage ----
        const float* sA = sm + s * STAGE_F;
        const float* sB = sA + AREG;
#pragma unroll
        for (int kt = 0; kt < 4; kt++) {
            uint32_t af[2][4], bf[8][2];
#pragma unroll
            for (int mt = 0; mt < 2; mt++) {
                float4 v = *reinterpret_cast<const float4*>(sA + a_off(kt, wy * 2 + mt, lane));
                af[mt][0] = __float_as_uint(v.x); af[mt][1] = __float_as_uint(v.y);
                af[mt][2] = __float_as_uint(v.z); af[mt][3] = __float_as_uint(v.w);
            }
#pragma unroll
            for (int nt = 0; nt < 8; nt++) {
                float2 v = *reinterpret_cast<const float2*>(sB + b_off(kt, wx * 8 + nt, lane));
                bf[nt][0] = __float_as_uint(v.x); bf[nt][1] = __float_as_uint(v.y);
            }
#pragma unroll
            for (int mt = 0; mt < 2; mt++)
#pragma unroll
                for (int nt = 0; nt < 8; nt++)
                    MMA_TF32(c[mt][nt], af[mt], bf[nt]);
        }
        // ---- store next chunk into other stage ----
        if (ci + 1 < nchunk) {
            float* dA = sm + (s ^ 1) * STAGE_F;
            float* dB = dA + AREG;
#pragma unroll
            for (int l = 0; l < 4; l++) {
                int idx = tid + l * 256, rr = idx >> 3, c4 = idx & 7;
                int kt = c4 >> 1, half = c4 & 1;
                int rt = rr >> 4, g = rr & 7, hi = (rr >> 3) & 1;
                int reg = hi + 2 * half;
                int ba = a_off(kt, rt, g * 4) + reg;
                dA[ba + 0] = ra[l].x; dA[ba + 4] = ra[l].y; dA[ba + 8] = ra[l].z; dA[ba + 12] = ra[l].w;
                int nt = rr >> 3, gb = rr & 7, regb = c4 & 1;
                int bb = b_off(kt, nt, gb * 4) + regb;
                dB[bb + 0] = rb[l].x; dB[bb + 2] = rb[l].y; dB[bb + 4] = rb[l].z; dB[bb + 6] = rb[l].w;
            }
        }
        __syncthreads();
    }

    // ---------------- epilogue ----------------
    // c[mt][nt][r]: row = bm0 + wy*32 + mt*16 + (r>>1)*8 + (lane>>2)
    //              col = bn0 + wx*64 + nt*8 + 2*(lane&3) + (r&1)
    const int g = lane >> 2, q = lane & 3;
    const int rb0 = bm0 + wy * 32;
    const int cb0 = bn0 + wx * 64;
    constexpr float NEG_INV2SIG2 = -1.0f / (2.0f * 32.0f * 32.0f);

    if (MODE == 0) {
#pragma unroll
        for (int mt = 0; mt < 2; mt++) {
#pragma unroll
            for (int hi = 0; hi < 2; hi++) {
                const int row = rb0 + mt * 16 + hi * 8 + g;
                const float sqi = g_sq[row];
                float rs = 0.f;
#pragma unroll
                for (int nt = 0; nt < 8; nt++) {
                    const int col = cb0 + nt * 8 + 2 * q;
                    float d0 = c[mt][nt][hi * 2 + 0];
                    float d1 = c[mt][nt][hi * 2 + 1];
                    float w0 = cvt_tf32_rn(__expf(fmaxf(sqi + g_sq[col + 0] - 2.f * d0, 0.f) * NEG_INV2SIG2));
                    float w1 = cvt_tf32_rn(__expf(fmaxf(sqi + g_sq[col + 1] - 2.f * d1, 0.f) * NEG_INV2SIG2));
                    rs += w0 + w1;
                    *reinterpret_cast<float2*>(C + (size_t)row * Ntot + col) = make_float2(w0, w1);
                }
                rs += __shfl_xor_sync(0xffffffffu, rs, 1);
                rs += __shfl_xor_sync(0xffffffffu, rs, 2);
                if (q == 0) atomicAdd(&g_rowsum[row], rs);
            }
        }
    } else if (MODE == 1) {
#pragma unroll
        for (int mt = 0; mt < 2; mt++) {
#pragma unroll
            for (int hi = 0; hi < 2; hi++) {
                const int row = rb0 + mt * 16 + hi * 8 + g;
                const float inv = 1.f / (g_rowsum[row] + 1e-8f);
#pragma unroll
                for (int nt = 0; nt < 8; nt++) {
                    const int col = cb0 + nt * 8 + 2 * q;
                    float v0 = cvt_tf32_rn(c[mt][nt][hi * 2 + 0] * inv);
                    float v1 = cvt_tf32_rn(c[mt][nt][hi * 2 + 1] * inv);
                    *reinterpret_cast<float2*>(C + (size_t)row * Ntot + col) = make_float2(v0, v1);
                }
            }
        }
    } else {
#pragma unroll
        for (int mt = 0; mt < 2; mt++) {
#pragma unroll
            for (int hi = 0; hi < 2; hi++) {
                const int row = rb0 + mt * 16 + hi * 8 + g;
#pragma unroll
                for (int nt = 0; nt < 8; nt++) {
                    const int col = cb0 + nt * 8 + 2 * q;
                    float v0 = c[mt][nt][hi * 2 + 0] + bias[col + 0];
                    float v1 = c[mt][nt][hi * 2 + 1] + bias[col + 1];
                    *reinterpret_cast<float2*>(C + (size_t)row * Ntot + col) = make_float2(v0, v1);
                }
            }
        }
    }
}

// ---------------- launch ----------------
extern "C" void kernel_launch(void* const* d_in, const int* in_sizes, int n_in,
                              void* d_out, int out_size)
{
    const float* x  = (const float*)d_in[0];   // [8192, 512]
    const float* Wl = (const float*)d_in[1];   // [512, 512]
    const float* b  = (const float*)d_in[2];   // [512]
    float* out = (float*)d_out;                // [8192, 512]

    void *wmat_p, *out1_p, *xr_p, *xT_p, *wlr_p;
    cudaGetSymbolAddress(&wmat_p, g_wmat);
    cudaGetSymbolAddress(&out1_p, g_out1);
    cudaGetSymbolAddress(&xr_p,   g_xr);
    cudaGetSymbolAddress(&xT_p,   g_xT);
    cudaGetSymbolAddress(&wlr_p,  g_wlr);

    const int SMEM_BYTES = 2 * 2 * 4128 * sizeof(float);   // 66048 B
    cudaFuncSetAttribute(hmma_gemm<0>, cudaFuncAttributeMaxDynamicSharedMemorySize, SMEM_BYTES);
    cudaFuncSetAttribute(hmma_gemm<1>, cudaFuncAttributeMaxDynamicSharedMemorySize, SMEM_BYTES);
    cudaFuncSetAttribute(hmma_gemm<2>, cudaFuncAttributeMaxDynamicSharedMemorySize, SMEM_BYTES);

    prep_x_kernel<<<NPTS / 8, 256>>>(x);
    transpose_kernel<<<dim3(NPTS / 32, DDIM / 32), 256>>>();
    prep_w_kernel<<<ODIM * DDIM / (256 * 4), 256>>>(Wl);

    // GEMM1: wmat = exp-weight(x . x^T), rowsums via atomics
    hmma_gemm<0><<<dim3(NPTS / 128, NPTS / 128), 256, SMEM_BYTES>>>(
        (const float*)xr_p, (const float*)xr_p, (float*)wmat_p, NPTS, DDIM, nullptr);
    // GEMM2: out1 = (wmat . x) / rowsum   (B = x^T as [DDIM, NPTS])
    hmma_gemm<1><<<dim3(DDIM / 128, NPTS / 128), 256, SMEM_BYTES>>>(
        (const float*)wmat_p, (const float*)xT_p, (float*)out1_p, DDIM, NPTS, nullptr);
    // GEMM3: out = out1 . Wl^T + b
    hmma_gemm<2><<<dim3(ODIM / 128, NPTS / 128), 256, SMEM_BYTES>>>(
        (const float*)out1_p, (const float*)wlr_p, out, ODIM, DDIM, b);
}